// round 15
// baseline (speedup 1.0000x reference)
#include <cuda_runtime.h>
#include <cuda_bf16.h>
#include <cuda_fp16.h>
#include <math.h>
#include <stdint.h>

// Problem constants
#define EMBED   512
#define HIDDEN  512
#define VOCAB   32000
#define NLAYERS 2
#define BATCH   32
#define SEQ     64
#define STEPS   (SEQ - 1)          // 63
#define MROWS   (STEPS * BATCH)    // 2016
#define MPAD    2048
#define KPA     1024               // A storage: [Ahi | Alo]
#define KB      512                // B storage: single fp16 copy
#define GUNITS  2048               // 4 gates x 512
#define SCAN_G  64                 // scan grid; 64 <= 148 SMs -> all resident
#define NCTR    8                  // split-barrier counters
#define CTRPAD  32                 // 128B line per counter
#define PLH     (HIDDEN * BATCH)   // 16384 halves per h plane

// ---------------- scratch (no allocations allowed) ----------------
__device__ __half g_A[(size_t)MPAD * KPA];             // 4.2 MB  [hi|lo]
__device__ __half g_B[(size_t)VOCAB * KB];             // 33 MB   out_w hi
__device__ __half g_BW[(size_t)NLAYERS * GUNITS * KB]; // 4.2 MB  Wx hi
__device__ float  g_X[(size_t)MPAD * GUNITS];          // 16.8 MB x-part preacts
// h state: [pingpong][hi/lo][b*512 + k] fp16 planes, per layer
__device__ __half g_hT0p[2][2][PLH];
__device__ __half g_hT1p[2][2][PLH];
__device__ float  g_c0T[HIDDEN * BATCH];
__device__ unsigned g_ctr[2][NCTR * CTRPAD];           // split grid-barrier counters
__device__ unsigned g_fin[2];

__device__ __forceinline__ float sigmoidf_(float x) {
    return 1.0f / (1.0f + expf(-x));
}

// ================= PTX helpers (baseline ISA only) =================
static __device__ __forceinline__ uint32_t smem_u32(const void* p) {
    uint32_t a;
    asm("{ .reg .u64 t; cvta.to.shared.u64 t, %1; cvt.u32.u64 %0, t; }" : "=r"(a) : "l"(p));
    return a;
}
static __device__ __forceinline__ void cp_async16(uint32_t dst, const void* src) {
    asm volatile("cp.async.cg.shared.global [%0], [%1], 16;" :: "r"(dst), "l"(src));
}
#define CP_COMMIT()  asm volatile("cp.async.commit_group;" ::: "memory")
#define CP_WAIT(n)   asm volatile("cp.async.wait_group %0;" :: "n"(n) : "memory")

static __device__ __forceinline__ void ldsm4(uint32_t* r, uint32_t addr) {
    asm volatile("ldmatrix.sync.aligned.m8n8.x4.shared.b16 {%0,%1,%2,%3}, [%4];"
                 : "=r"(r[0]), "=r"(r[1]), "=r"(r[2]), "=r"(r[3]) : "r"(addr));
}
static __device__ __forceinline__ void mma16816(float* c, const uint32_t* a,
                                                uint32_t b0, uint32_t b1) {
    asm volatile("mma.sync.aligned.m16n8k16.row.col.f32.f16.f16.f32 "
                 "{%0,%1,%2,%3}, {%4,%5,%6,%7}, {%8,%9}, {%0,%1,%2,%3};"
                 : "+f"(c[0]), "+f"(c[1]), "+f"(c[2]), "+f"(c[3])
                 : "r"(a[0]), "r"(a[1]), "r"(a[2]), "r"(a[3]), "r"(b0), "r"(b1));
}

// ---------------- init: h0/c0 -> fp16 hi/lo state planes ----------------
__global__ void init_kernel(const float* __restrict__ features,
                            const float* __restrict__ ihw, const float* __restrict__ ihb,
                            const float* __restrict__ icw, const float* __restrict__ icb) {
    __shared__ float feat[EMBED];
    int b = blockIdx.x;
    for (int i = threadIdx.x; i < EMBED; i += blockDim.x)
        feat[i] = features[b * EMBED + i];
    __syncthreads();

    for (int j = threadIdx.x; j < HIDDEN; j += blockDim.x) {
        float ah = ihb[j];
        float ac = icb[j];
        const float4* wh = (const float4*)(ihw + (size_t)j * EMBED);
        const float4* wc = (const float4*)(icw + (size_t)j * EMBED);
        #pragma unroll 4
        for (int e4 = 0; e4 < EMBED / 4; e4++) {
            float4 h4 = wh[e4];
            float4 c4 = wc[e4];
            const float* f = &feat[e4 * 4];
            ah += f[0]*h4.x + f[1]*h4.y + f[2]*h4.z + f[3]*h4.w;
            ac += f[0]*c4.x + f[1]*c4.y + f[2]*c4.z + f[3]*c4.w;
        }
        __half hhi = __float2half_rn(ah);
        __half hlo = __float2half_rn(ah - __half2float(hhi));
        g_hT0p[0][0][b * 512 + j] = hhi;
        g_hT0p[0][1][b * 512 + j] = hlo;
        g_hT1p[0][0][b * 512 + j] = hhi;
        g_hT1p[0][1][b * 512 + j] = hlo;
        g_c0T[j * BATCH + b]      = ac;
    }
}

// ---------------- conversions ----------------
// out_w -> g_B (hi only, K=512); float4-vectorized streaming
__global__ __launch_bounds__(256)
void convB_kernel(const float* __restrict__ w) {
    size_t idx4 = (size_t)blockIdx.x * blockDim.x + threadIdx.x;
    if (idx4 >= (size_t)VOCAB * 512 / 4) return;
    float4 v = ((const float4*)w)[idx4];
    __half2 h01 = __floats2half2_rn(v.x, v.y);
    __half2 h23 = __floats2half2_rn(v.z, v.w);
    __half2* dst = (__half2*)g_B + idx4 * 2;
    dst[0] = h01;
    dst[1] = h23;
}

// Wx (x-part of gate weights, both layers) -> g_BW (hi only, row stride 512)
__global__ __launch_bounds__(256)
void convWx_kernel(const float* __restrict__ Wf, const float* __restrict__ Wi,
                   const float* __restrict__ Wo, const float* __restrict__ Wc) {
    size_t idx = (size_t)blockIdx.x * blockDim.x + threadIdx.x;
    if (idx >= (size_t)NLAYERS * GUNITS * 512) return;
    int k = (int)(idx & 511);
    int r = (int)((idx >> 9) & (GUNITS - 1));
    int l = (int)(idx >> 20);              // 2048*512 = 2^20
    int g = r >> 9;
    int j = r & 511;
    const float* W = (g == 0) ? Wf : (g == 1) ? Wi : (g == 2) ? Wo : Wc;
    g_BW[((size_t)l * GUNITS + r) * KB + k] =
        __float2half_rn(W[(size_t)l * HIDDEN * 1024 + (size_t)j * 1024 + k]);
}

// embeddings gather -> g_A (A-style: [hi | lo]); row m = t*32+b
__global__ __launch_bounds__(256)
void embA_kernel(const int* __restrict__ captions, const float* __restrict__ embw) {
    size_t idx = (size_t)blockIdx.x * blockDim.x + threadIdx.x;
    if (idx >= (size_t)MROWS * 512) return;
    int m = (int)(idx >> 9);
    int k = (int)(idx & 511);
    int t = m >> 5, b = m & 31;
    int tok = captions[b * SEQ + t];
    float x = embw[(size_t)tok * EMBED + k];
    __half hi = __float2half_rn(x);
    __half lo = __float2half_rn(x - __half2float(hi));
    size_t base = (size_t)m * KPA;
    g_A[base + k]       = hi;
    g_A[base + 512 + k] = lo;
}

// ---------------- generic split HMMA GEMM (unchanged, proven) ----------------
#define GBK       64
#define GTILE_B   16384              // 128 rows * 128 B
#define GBUF_B    (2 * GTILE_B)
#define SMEM_DYN  (2 * GBUF_B + 512)

__global__ __launch_bounds__(256)
void gemm_split_kernel(const __half* __restrict__ Bsrc, const float* __restrict__ bias,
                       float* __restrict__ C, int N, int permute, int nch, int nchB) {
    extern __shared__ __align__(128) char sm[];
    const uint32_t smu = smem_u32(sm);
    float* bias_s = (float*)(sm + 2 * GBUF_B);

    const int tid  = threadIdx.x;
    const int wid  = tid >> 5;
    const int lane = tid & 31;
    const int n0 = blockIdx.x * 128;
    const int m0 = blockIdx.y * 128;

    const int warp_m = (wid >> 1) * 32;
    const int warp_n = (wid & 1) * 64;

    if (tid < 128) bias_s[tid] = bias ? bias[n0 + tid] : 0.0f;

    auto load_chunk = [&](int c) {
        const int buf = c & 1;
        const int cb = c & (nchB - 1);
        const uint32_t sA = smu + buf * GBUF_B;
        const uint32_t sB = sA + GTILE_B;
        const __half* Ag = g_A + (size_t)m0 * KPA + c * GBK;
        const __half* Bg = Bsrc + (size_t)n0 * KB + cb * GBK;
        #pragma unroll
        for (int i = 0; i < 4; i++) {
            int idx = i * 256 + tid;
            int r  = idx >> 3;
            int ch = idx & 7;
            uint32_t dst = (uint32_t)(r * 128) + (((uint32_t)(ch ^ (r & 7))) << 4);
            cp_async16(sA + dst, Ag + (size_t)r * KPA + ch * 8);
            cp_async16(sB + dst, Bg + (size_t)r * KB + ch * 8);
        }
        CP_COMMIT();
    };

    float acc[2][8][4];
    #pragma unroll
    for (int mi = 0; mi < 2; mi++)
        #pragma unroll
        for (int ni = 0; ni < 8; ni++)
            #pragma unroll
            for (int q = 0; q < 4; q++) acc[mi][ni][q] = 0.f;

    load_chunk(0);
    load_chunk(1);

    for (int c = 0; c < nch; c++) {
        if (c + 1 < nch) { CP_WAIT(1); } else { CP_WAIT(0); }
        __syncthreads();

        const int buf = c & 1;
        const uint32_t sA = smu + buf * GBUF_B;
        const uint32_t sB = sA + GTILE_B;

        #pragma unroll
        for (int ks = 0; ks < GBK / 16; ks++) {
            uint32_t a[2][4];
            #pragma unroll
            for (int mi = 0; mi < 2; mi++) {
                int row = warp_m + mi * 16 + (lane & 15);
                int kc  = ks * 2 + (lane >> 4);
                uint32_t addr = sA + row * 128 + (((uint32_t)(kc ^ (row & 7))) << 4);
                ldsm4(a[mi], addr);
            }
            uint32_t bfr[4][4];
            #pragma unroll
            for (int nj = 0; nj < 4; nj++) {
                int row = warp_n + nj * 16 + (lane & 7) + ((lane >> 4) << 3);
                int kc  = ks * 2 + ((lane >> 3) & 1);
                uint32_t addr = sB + row * 128 + (((uint32_t)(kc ^ (row & 7))) << 4);
                ldsm4(bfr[nj], addr);
            }
            #pragma unroll
            for (int mi = 0; mi < 2; mi++)
                #pragma unroll
                for (int ni = 0; ni < 8; ni++) {
                    const uint32_t* bp = &bfr[ni >> 1][(ni & 1) * 2];
                    mma16816(acc[mi][ni], a[mi], bp[0], bp[1]);
                }
        }
        __syncthreads();
        if (c + 2 < nch) load_chunk(c + 2);
    }

    #pragma unroll
    for (int mi = 0; mi < 2; mi++) {
        int r0 = m0 + warp_m + mi * 16 + (lane >> 2);
        int r1 = r0 + 8;
        float* orow0 = nullptr;
        float* orow1 = nullptr;
        if (permute) {
            if (r0 < MROWS) {
                int bb = r0 & 31, tt = r0 >> 5;
                orow0 = C + (size_t)(bb * STEPS + tt) * N + n0;
            }
            if (r1 < MROWS) {
                int bb = r1 & 31, tt = r1 >> 5;
                orow1 = C + (size_t)(bb * STEPS + tt) * N + n0;
            }
        } else {
            orow0 = C + (size_t)r0 * N + n0;
            orow1 = C + (size_t)r1 * N + n0;
        }
        #pragma unroll
        for (int ni = 0; ni < 8; ni++) {
            int col = warp_n + ni * 8 + (lane & 3) * 2;
            float b0 = bias_s[col];
            float b1 = bias_s[col + 1];
            if (orow0) {
                float2 v; v.x = acc[mi][ni][0] + b0; v.y = acc[mi][ni][1] + b1;
                *(float2*)&orow0[col] = v;
            }
            if (orow1) {
                float2 v; v.x = acc[mi][ni][2] + b0; v.y = acc[mi][ni][3] + b1;
                *(float2*)&orow1[col] = v;
            }
        }
    }
}

// ---------------- persistent tensor-core scan: 63 steps of one layer ----------------
// 64 blocks x 128 threads, 1/SM guaranteed resident. Block owns 8 units x 4 gates
// (32 W rows). Per step: gates = h~ @ W~^T via mma.sync with exact 3-term split
// (A=[hi(h)|lo(h)|hi(h)], B=[hi(W)|hi(W)|lo(W)], K'=1536, error ~2^-22).
// W smem-resident fp16 swizzled (64 KB); h staged per step via cp.async (64 KB).
#define SCAN_SMEM (65536 + 65536 + 4096 + 256)

__global__ __launch_bounds__(128, 1)
void scan_kernel(const float* __restrict__ Wf, const float* __restrict__ Wi,
                 const float* __restrict__ Wo, const float* __restrict__ Wc,
                 const float* __restrict__ bfv, const float* __restrict__ biv,
                 const float* __restrict__ bov, const float* __restrict__ bcv,
                 const float* __restrict__ X, __half* __restrict__ hT,
                 const float* __restrict__ c0T, int layer) {
    extern __shared__ __align__(128) char sm[];
    __half* A_s = (__half*)sm;                       // 16 chunks x 4 KB (h hi|lo)
    __half* B_s = (__half*)(sm + 65536);             // 16 chunks x 4 KB (W hi|lo)
    float*  D_s = (float*)(sm + 131072);             // [32 b][32 n]
    float*  bias_s = (float*)(sm + 131072 + 4096);   // [32]
    const uint32_t Au = smem_u32(A_s);
    const uint32_t Bu = smem_u32(B_s);

    const int tid = threadIdx.x;
    const int bid = blockIdx.x;
    const int lane = tid & 31;
    const int wid = tid >> 5;
    const int warp_m = (wid >> 1) * 16;   // batch rows 0-15 / 16-31
    const int warp_n = (wid & 1) * 16;    // gate-unit cols 0-15 / 16-31

    // ---- one-time: load W h-part rows (32) as fp16 hi/lo, swizzled ----
    for (int i = tid; i < 32 * 512; i += 128) {
        int n = i >> 9;          // 0..31 : g*8+u
        int k = i & 511;
        int g = n >> 3, u = n & 7;
        const float* W = (g == 0) ? Wf : (g == 1) ? Wi : (g == 2) ? Wo : Wc;
        float w = W[(size_t)(bid * 8 + u) * 1024 + 512 + k];
        __half hi = __float2half_rn(w);
        __half lo = __float2half_rn(w - __half2float(hi));
        int p  = k >> 6;         // physical chunk 0..7
        int kk = k & 63;
        int g8 = kk >> 3;
        int off = n * 128 + ((g8 ^ (n & 7)) << 4) + (kk & 7) * 2;
        *(__half*)((char*)B_s + p * 4096 + off)       = hi;   // chunks 0-7: hi
        *(__half*)((char*)B_s + (8 + p) * 4096 + off) = lo;   // chunks 8-15: lo
    }
    if (tid < 32) {
        int g = tid >> 3, u = tid & 7;
        const float* Bv = (g == 0) ? bfv : (g == 1) ? biv : (g == 2) ? bov : bcv;
        bias_s[tid] = Bv[bid * 8 + u];
    }
    float c_reg0 = c0T[(bid * 8 + (tid >> 5)) * BATCH + (tid & 31)];
    float c_reg1 = c0T[(bid * 8 + 4 + (tid >> 5)) * BATCH + (tid & 31)];
    __syncthreads();

    const unsigned per_ctr = SCAN_G / NCTR;   // 8 arrivals per counter per step

    for (int t = 0; t < STEPS; t++) {
        const int p = t & 1;
        const __half* hc_hi = hT + (p * 2 + 0) * PLH;
        const __half* hc_lo = hT + (p * 2 + 1) * PLH;
        __half* hn_hi = hT + ((p ^ 1) * 2 + 0) * PLH;
        __half* hn_lo = hT + ((p ^ 1) * 2 + 1) * PLH;

        // ---- stage h: 16 chunks (hi 0-7, lo 8-15), swizzled [b][64k] tiles ----
        #pragma unroll
        for (int c = 0; c < 16; c++) {
            const __half* src = ((c < 8) ? hc_hi : hc_lo) + (c & 7) * 64;
            #pragma unroll
            for (int r = 0; r < 2; r++) {
                int idx = tid + 128 * r;          // 0..255
                int b  = idx >> 3;
                int g8 = idx & 7;
                uint32_t dst = Au + c * 4096 + b * 128 + (uint32_t)((g8 ^ (b & 7)) << 4);
                cp_async16(dst, src + b * 512 + g8 * 8);
            }
        }
        CP_COMMIT();
        CP_WAIT(0);
        __syncthreads();

        // ---- mma over 24 logical chunks (A: hi,lo,hi ; B: hi,hi,lo) ----
        float acc[2][4];
        #pragma unroll
        for (int ni = 0; ni < 2; ni++)
            #pragma unroll
            for (int q = 0; q < 4; q++) acc[ni][q] = 0.f;

        #pragma unroll 1
        for (int c = 0; c < 24; c++) {
            int pa = (c < 16) ? c : (c - 16);
            int pb = (c < 8) ? c : (c - 8);
            uint32_t Ab = Au + pa * 4096;
            uint32_t Bb = Bu + pb * 4096;
            #pragma unroll
            for (int ks = 0; ks < 4; ks++) {
                uint32_t a[4];
                {
                    int row = warp_m + (lane & 15);
                    int kc  = ks * 2 + (lane >> 4);
                    ldsm4(a, Ab + row * 128 + (uint32_t)((kc ^ (row & 7)) << 4));
                }
                uint32_t bb[4];
                {
                    int row = warp_n + (lane & 7) + ((lane >> 4) << 3);
                    int kc  = ks * 2 + ((lane >> 3) & 1);
                    ldsm4(bb, Bb + row * 128 + (uint32_t)((kc ^ (row & 7)) << 4));
                }
                mma16816(acc[0], a, bb[0], bb[1]);
                mma16816(acc[1], a, bb[2], bb[3]);
            }
        }

        // ---- exchange D through smem: D_s[b][n] ----
        {
            int r0 = warp_m + (lane >> 2);
            int cc = warp_n + (lane & 3) * 2;
            D_s[r0 * 32 + cc]           = acc[0][0];
            D_s[r0 * 32 + cc + 1]       = acc[0][1];
            D_s[(r0 + 8) * 32 + cc]     = acc[0][2];
            D_s[(r0 + 8) * 32 + cc + 1] = acc[0][3];
            D_s[r0 * 32 + cc + 8]           = acc[1][0];
            D_s[r0 * 32 + cc + 9]           = acc[1][1];
            D_s[(r0 + 8) * 32 + cc + 8]     = acc[1][2];
            D_s[(r0 + 8) * 32 + cc + 9]     = acc[1][3];
        }
        __syncthreads();

        // ---- state update: 2 (unit, batch) states per thread ----
        #pragma unroll
        for (int s = 0; s < 2; s++) {
            int st = tid + s * 128;
            int u = st >> 5, b = st & 31;
            int jg = bid * 8 + u;
            const float* xrow = X + (size_t)(t * BATCH + b) * GUNITS + jg;
            float fv = sigmoidf_(D_s[b * 32 + u]      + bias_s[u]      + xrow[0]);
            float iv = sigmoidf_(D_s[b * 32 + 8 + u]  + bias_s[8 + u]  + xrow[512]);
            float ov = sigmoidf_(D_s[b * 32 + 16 + u] + bias_s[16 + u] + xrow[1024]);
            float cv = tanhf    (D_s[b * 32 + 24 + u] + bias_s[24 + u] + xrow[1536]);
            float cr = s ? c_reg1 : c_reg0;
            cr = fv * cr + iv * cv;
            if (s) c_reg1 = cr; else c_reg0 = cr;
            float h = ov * tanhf(cr);
            __half hhi = __float2half_rn(h);
            __half hlo = __float2half_rn(h - __half2float(hhi));
            hn_hi[b * 512 + jg] = hhi;
            hn_lo[b * 512 + jg] = hlo;
            size_t ab = (size_t)(t * BATCH + b) * KPA + jg;
            g_A[ab]       = hhi;
            g_A[ab + 512] = hlo;
        }
        __syncthreads();

        // ---- grid barrier (split counters, 64 arrivals) ----
        if (tid == 0) {
            __threadfence();
            atomicAdd(&g_ctr[layer][(bid & (NCTR - 1)) * CTRPAD], 1u);
        }
        if (tid < NCTR) {
            unsigned target = (unsigned)(t + 1) * per_ctr;
            volatile unsigned* pc = &g_ctr[layer][tid * CTRPAD];
            while (*pc < target) { __nanosleep(32); }
            __threadfence();
        }
        __syncthreads();
    }

    // reset counters for next launch/replay (last block to finish does it)
    if (tid == 0) {
        unsigned v = atomicAdd(&g_fin[layer], 1u);
        if (v == SCAN_G - 1) {
            #pragma unroll
            for (int i = 0; i < NCTR; i++)
                g_ctr[layer][i * CTRPAD] = 0;
            g_fin[layer] = 0;
            __threadfence();
        }
    }
}

// ---------------- launch ----------------
extern "C" void kernel_launch(void* const* d_in, const int* in_sizes, int n_in,
                              void* d_out, int out_size) {
    const float* features = (const float*)d_in[0];
    const int*   captions = (const int*)  d_in[1];
    const float* embw     = (const float*)d_in[2];
    const float* Wf       = (const float*)d_in[3];
    const float* bf       = (const float*)d_in[4];
    const float* Wi       = (const float*)d_in[5];
    const float* bi       = (const float*)d_in[6];
    const float* Wc       = (const float*)d_in[7];
    const float* bc       = (const float*)d_in[8];
    const float* Wo       = (const float*)d_in[9];
    const float* bo       = (const float*)d_in[10];
    const float* out_w    = (const float*)d_in[11];
    const float* out_b    = (const float*)d_in[12];
    const float* ihw      = (const float*)d_in[13];
    const float* ihb      = (const float*)d_in[14];
    const float* icw      = (const float*)d_in[15];
    const float* icb      = (const float*)d_in[16];
    float* out = (float*)d_out;

    cudaFuncSetAttribute(gemm_split_kernel,
                         cudaFuncAttributeMaxDynamicSharedMemorySize, SMEM_DYN);
    cudaFuncSetAttribute(scan_kernel,
                         cudaFuncAttributeMaxDynamicSharedMemorySize, SCAN_SMEM);

    __half* g_B_ptr;  cudaGetSymbolAddress((void**)&g_B_ptr,  g_B);
    __half* g_BW_ptr; cudaGetSymbolAddress((void**)&g_BW_ptr, g_BW);
    float*  g_X_ptr;  cudaGetSymbolAddress((void**)&g_X_ptr,  g_X);
    __half* g_hT0_p;  cudaGetSymbolAddress((void**)&g_hT0_p,  g_hT0p);
    __half* g_hT1_p;  cudaGetSymbolAddress((void**)&g_hT1_p,  g_hT1p);
    float*  g_c0T_p;  cudaGetSymbolAddress((void**)&g_c0T_p,  g_c0T);

    // 1. init state
    init_kernel<<<BATCH, 256>>>(features, ihw, ihb, icw, icb);

    // 2. conversions (weights; independent of recurrence)
    convB_kernel<<<(VOCAB * 512 / 4 + 255) / 256, 256>>>(out_w);
    convWx_kernel<<<(NLAYERS * GUNITS * 512 + 255) / 256, 256>>>(Wf, Wi, Wo, Wc);
    embA_kernel<<<(MROWS * 512 + 255) / 256, 256>>>(captions, embw);

    // 3. X0 = emb @ Wx0^T  (2-term: A=[hi|lo], B chunk wraps modulo 8)
    {
        dim3 grid(GUNITS / 128, MPAD / 128);  // 16 x 16
        gemm_split_kernel<<<grid, 256, SMEM_DYN>>>(g_BW_ptr, nullptr, g_X_ptr,
                                                   GUNITS, 0, 16, 8);
    }

    // 4. layer-0 scan (persistent tensor-core; writes g_A hi/lo rows for X1)
    scan_kernel<<<SCAN_G, 128, SCAN_SMEM>>>(Wf, Wi, Wo, Wc, bf, bi, bo, bc,
                                            g_X_ptr, g_hT0_p, g_c0T_p, 0);

    // 5. X1 = h0 @ Wx1^T
    {
        dim3 grid(GUNITS / 128, MPAD / 128);
        gemm_split_kernel<<<grid, 256, SMEM_DYN>>>(g_BW_ptr + (size_t)GUNITS * KB,
                                                   nullptr, g_X_ptr, GUNITS, 0, 16, 8);
    }

    // 6. layer-1 scan (writes g_A hi/lo rows for logits)
    scan_kernel<<<SCAN_G, 128, SCAN_SMEM>>>(Wf + 512 * 1024, Wi + 512 * 1024,
                                            Wo + 512 * 1024, Wc + 512 * 1024,
                                            bf + 512, bi + 512, bo + 512, bc + 512,
                                            g_X_ptr, g_hT1_p, g_c0T_p, 1);

    // 7. logits = h1 @ out_w^T + out_b  (single-term fp16, permuted store)
    {
        dim3 grid(VOCAB / 128, MPAD / 128);   // 250 x 16
        gemm_split_kernel<<<grid, 256, SMEM_DYN>>>(g_B_ptr, out_b, out,
                                                   VOCAB, 1, 8, 8);
    }
}

// round 16
// speedup vs baseline: 1.1998x; 1.1998x over previous
#include <cuda_runtime.h>
#include <cuda_bf16.h>
#include <cuda_fp16.h>
#include <math.h>
#include <stdint.h>

// Problem constants
#define EMBED   512
#define HIDDEN  512
#define VOCAB   32000
#define NLAYERS 2
#define BATCH   32
#define SEQ     64
#define STEPS   (SEQ - 1)          // 63
#define MROWS   (STEPS * BATCH)    // 2016
#define MPAD    2048
#define KPA     1024               // A storage: [Ahi | Alo]
#define KB      512                // B storage: single fp16 copy
#define GUNITS  2048               // 4 gates x 512
#define SCAN_G  64                 // scan grid; 64 <= 148 SMs -> all resident
#define NCTR    8                  // split-barrier counters
#define CTRPAD  32                 // 128B line per counter
#define PLH     (HIDDEN * BATCH)   // 16384 halves per h plane

// ---------------- scratch (no allocations allowed) ----------------
__device__ __half g_A[(size_t)MPAD * KPA];             // 4.2 MB  [hi|lo]
__device__ __half g_B[(size_t)VOCAB * KB];             // 33 MB   out_w hi
__device__ __half g_BW[(size_t)NLAYERS * GUNITS * KB]; // 4.2 MB  Wx hi
__device__ float  g_X[(size_t)MPAD * GUNITS];          // 16.8 MB x-part preacts
// h state: [pingpong][hi/lo][b*512 + k] fp16 planes, per layer
__device__ __half g_hT0p[2][2][PLH];
__device__ __half g_hT1p[2][2][PLH];
__device__ float  g_c0T[HIDDEN * BATCH];
__device__ unsigned g_ctr[2][NCTR * CTRPAD];           // split grid-barrier counters
__device__ unsigned g_fin[2];

__device__ __forceinline__ float sigmoidf_(float x) {
    return 1.0f / (1.0f + expf(-x));
}

// ================= PTX helpers (baseline ISA only) =================
static __device__ __forceinline__ uint32_t smem_u32(const void* p) {
    uint32_t a;
    asm("{ .reg .u64 t; cvta.to.shared.u64 t, %1; cvt.u32.u64 %0, t; }" : "=r"(a) : "l"(p));
    return a;
}
static __device__ __forceinline__ void cp_async16(uint32_t dst, const void* src) {
    asm volatile("cp.async.cg.shared.global [%0], [%1], 16;" :: "r"(dst), "l"(src));
}
#define CP_COMMIT()  asm volatile("cp.async.commit_group;" ::: "memory")
#define CP_WAIT(n)   asm volatile("cp.async.wait_group %0;" :: "n"(n) : "memory")

static __device__ __forceinline__ void ldsm4(uint32_t* r, uint32_t addr) {
    asm volatile("ldmatrix.sync.aligned.m8n8.x4.shared.b16 {%0,%1,%2,%3}, [%4];"
                 : "=r"(r[0]), "=r"(r[1]), "=r"(r[2]), "=r"(r[3]) : "r"(addr));
}
static __device__ __forceinline__ void mma16816(float* c, const uint32_t* a,
                                                uint32_t b0, uint32_t b1) {
    asm volatile("mma.sync.aligned.m16n8k16.row.col.f32.f16.f16.f32 "
                 "{%0,%1,%2,%3}, {%4,%5,%6,%7}, {%8,%9}, {%0,%1,%2,%3};"
                 : "+f"(c[0]), "+f"(c[1]), "+f"(c[2]), "+f"(c[3])
                 : "r"(a[0]), "r"(a[1]), "r"(a[2]), "r"(a[3]), "r"(b0), "r"(b1));
}

// ---------------- init: h0/c0 -> fp16 hi/lo state planes ----------------
__global__ void init_kernel(const float* __restrict__ features,
                            const float* __restrict__ ihw, const float* __restrict__ ihb,
                            const float* __restrict__ icw, const float* __restrict__ icb) {
    __shared__ float feat[EMBED];
    int b = blockIdx.x;
    for (int i = threadIdx.x; i < EMBED; i += blockDim.x)
        feat[i] = features[b * EMBED + i];
    __syncthreads();

    for (int j = threadIdx.x; j < HIDDEN; j += blockDim.x) {
        float ah = ihb[j];
        float ac = icb[j];
        const float4* wh = (const float4*)(ihw + (size_t)j * EMBED);
        const float4* wc = (const float4*)(icw + (size_t)j * EMBED);
        #pragma unroll 4
        for (int e4 = 0; e4 < EMBED / 4; e4++) {
            float4 h4 = wh[e4];
            float4 c4 = wc[e4];
            const float* f = &feat[e4 * 4];
            ah += f[0]*h4.x + f[1]*h4.y + f[2]*h4.z + f[3]*h4.w;
            ac += f[0]*c4.x + f[1]*c4.y + f[2]*c4.z + f[3]*c4.w;
        }
        __half hhi = __float2half_rn(ah);
        __half hlo = __float2half_rn(ah - __half2float(hhi));
        g_hT0p[0][0][b * 512 + j] = hhi;
        g_hT0p[0][1][b * 512 + j] = hlo;
        g_hT1p[0][0][b * 512 + j] = hhi;
        g_hT1p[0][1][b * 512 + j] = hlo;
        g_c0T[j * BATCH + b]      = ac;
    }
}

// ---------------- conversions ----------------
// out_w -> g_B (hi only, K=512); float4-vectorized streaming
__global__ __launch_bounds__(256)
void convB_kernel(const float* __restrict__ w) {
    size_t idx4 = (size_t)blockIdx.x * blockDim.x + threadIdx.x;
    if (idx4 >= (size_t)VOCAB * 512 / 4) return;
    float4 v = ((const float4*)w)[idx4];
    __half2 h01 = __floats2half2_rn(v.x, v.y);
    __half2 h23 = __floats2half2_rn(v.z, v.w);
    __half2* dst = (__half2*)g_B + idx4 * 2;
    dst[0] = h01;
    dst[1] = h23;
}

// Wx (x-part of gate weights, both layers) -> g_BW (hi only, row stride 512)
__global__ __launch_bounds__(256)
void convWx_kernel(const float* __restrict__ Wf, const float* __restrict__ Wi,
                   const float* __restrict__ Wo, const float* __restrict__ Wc) {
    size_t idx = (size_t)blockIdx.x * blockDim.x + threadIdx.x;
    if (idx >= (size_t)NLAYERS * GUNITS * 512) return;
    int k = (int)(idx & 511);
    int r = (int)((idx >> 9) & (GUNITS - 1));
    int l = (int)(idx >> 20);              // 2048*512 = 2^20
    int g = r >> 9;
    int j = r & 511;
    const float* W = (g == 0) ? Wf : (g == 1) ? Wi : (g == 2) ? Wo : Wc;
    g_BW[((size_t)l * GUNITS + r) * KB + k] =
        __float2half_rn(W[(size_t)l * HIDDEN * 1024 + (size_t)j * 1024 + k]);
}

// embeddings gather -> g_A (A-style: [hi | lo]); row m = t*32+b
__global__ __launch_bounds__(256)
void embA_kernel(const int* __restrict__ captions, const float* __restrict__ embw) {
    size_t idx = (size_t)blockIdx.x * blockDim.x + threadIdx.x;
    if (idx >= (size_t)MROWS * 512) return;
    int m = (int)(idx >> 9);
    int k = (int)(idx & 511);
    int t = m >> 5, b = m & 31;
    int tok = captions[b * SEQ + t];
    float x = embw[(size_t)tok * EMBED + k];
    __half hi = __float2half_rn(x);
    __half lo = __float2half_rn(x - __half2float(hi));
    size_t base = (size_t)m * KPA;
    g_A[base + k]       = hi;
    g_A[base + 512 + k] = lo;
}

// ---------------- generic split HMMA GEMM (unchanged, proven) ----------------
#define GBK       64
#define GTILE_B   16384              // 128 rows * 128 B
#define GBUF_B    (2 * GTILE_B)
#define SMEM_DYN  (2 * GBUF_B + 512)

__global__ __launch_bounds__(256)
void gemm_split_kernel(const __half* __restrict__ Bsrc, const float* __restrict__ bias,
                       float* __restrict__ C, int N, int permute, int nch, int nchB) {
    extern __shared__ __align__(128) char sm[];
    const uint32_t smu = smem_u32(sm);
    float* bias_s = (float*)(sm + 2 * GBUF_B);

    const int tid  = threadIdx.x;
    const int wid  = tid >> 5;
    const int lane = tid & 31;
    const int n0 = blockIdx.x * 128;
    const int m0 = blockIdx.y * 128;

    const int warp_m = (wid >> 1) * 32;
    const int warp_n = (wid & 1) * 64;

    if (tid < 128) bias_s[tid] = bias ? bias[n0 + tid] : 0.0f;

    auto load_chunk = [&](int c) {
        const int buf = c & 1;
        const int cb = c & (nchB - 1);
        const uint32_t sA = smu + buf * GBUF_B;
        const uint32_t sB = sA + GTILE_B;
        const __half* Ag = g_A + (size_t)m0 * KPA + c * GBK;
        const __half* Bg = Bsrc + (size_t)n0 * KB + cb * GBK;
        #pragma unroll
        for (int i = 0; i < 4; i++) {
            int idx = i * 256 + tid;
            int r  = idx >> 3;
            int ch = idx & 7;
            uint32_t dst = (uint32_t)(r * 128) + (((uint32_t)(ch ^ (r & 7))) << 4);
            cp_async16(sA + dst, Ag + (size_t)r * KPA + ch * 8);
            cp_async16(sB + dst, Bg + (size_t)r * KB + ch * 8);
        }
        CP_COMMIT();
    };

    float acc[2][8][4];
    #pragma unroll
    for (int mi = 0; mi < 2; mi++)
        #pragma unroll
        for (int ni = 0; ni < 8; ni++)
            #pragma unroll
            for (int q = 0; q < 4; q++) acc[mi][ni][q] = 0.f;

    load_chunk(0);
    load_chunk(1);

    for (int c = 0; c < nch; c++) {
        if (c + 1 < nch) { CP_WAIT(1); } else { CP_WAIT(0); }
        __syncthreads();

        const int buf = c & 1;
        const uint32_t sA = smu + buf * GBUF_B;
        const uint32_t sB = sA + GTILE_B;

        #pragma unroll
        for (int ks = 0; ks < GBK / 16; ks++) {
            uint32_t a[2][4];
            #pragma unroll
            for (int mi = 0; mi < 2; mi++) {
                int row = warp_m + mi * 16 + (lane & 15);
                int kc  = ks * 2 + (lane >> 4);
                uint32_t addr = sA + row * 128 + (((uint32_t)(kc ^ (row & 7))) << 4);
                ldsm4(a[mi], addr);
            }
            uint32_t bfr[4][4];
            #pragma unroll
            for (int nj = 0; nj < 4; nj++) {
                int row = warp_n + nj * 16 + (lane & 7) + ((lane >> 4) << 3);
                int kc  = ks * 2 + ((lane >> 3) & 1);
                uint32_t addr = sB + row * 128 + (((uint32_t)(kc ^ (row & 7))) << 4);
                ldsm4(bfr[nj], addr);
            }
            #pragma unroll
            for (int mi = 0; mi < 2; mi++)
                #pragma unroll
                for (int ni = 0; ni < 8; ni++) {
                    const uint32_t* bp = &bfr[ni >> 1][(ni & 1) * 2];
                    mma16816(acc[mi][ni], a[mi], bp[0], bp[1]);
                }
        }
        __syncthreads();
        if (c + 2 < nch) load_chunk(c + 2);
    }

    #pragma unroll
    for (int mi = 0; mi < 2; mi++) {
        int r0 = m0 + warp_m + mi * 16 + (lane >> 2);
        int r1 = r0 + 8;
        float* orow0 = nullptr;
        float* orow1 = nullptr;
        if (permute) {
            if (r0 < MROWS) {
                int bb = r0 & 31, tt = r0 >> 5;
                orow0 = C + (size_t)(bb * STEPS + tt) * N + n0;
            }
            if (r1 < MROWS) {
                int bb = r1 & 31, tt = r1 >> 5;
                orow1 = C + (size_t)(bb * STEPS + tt) * N + n0;
            }
        } else {
            orow0 = C + (size_t)r0 * N + n0;
            orow1 = C + (size_t)r1 * N + n0;
        }
        #pragma unroll
        for (int ni = 0; ni < 8; ni++) {
            int col = warp_n + ni * 8 + (lane & 3) * 2;
            float b0 = bias_s[col];
            float b1 = bias_s[col + 1];
            if (orow0) {
                float2 v; v.x = acc[mi][ni][0] + b0; v.y = acc[mi][ni][1] + b1;
                *(float2*)&orow0[col] = v;
            }
            if (orow1) {
                float2 v; v.x = acc[mi][ni][2] + b0; v.y = acc[mi][ni][3] + b1;
                *(float2*)&orow1[col] = v;
            }
        }
    }
}

// ---------------- persistent tensor-core scan v2 ----------------
// 64 blocks x 256 threads. 2-term split (drop hi(h)*lo(W), same scheme the X
// GEMMs use): A=[hi(h)|lo(h)], B=[hi(W)]. Warp-split: warps 0-3 compute the
// hi(h) half, warps 4-7 the lo(h) half, partial sums in D_s[2] (stride 33 —
// conflict-free update reads). W hi smem-resident (32 KB); h staged per step
// via cp.async (64 KB).
#define SCAN_T    256
#define DS_OFF    (65536 + 32768)
#define SCAN_SMEM (DS_OFF + 8448 + 128)   // A 64K + B 32K + D 2*32*33*4 + bias

__global__ __launch_bounds__(SCAN_T, 1)
void scan_kernel(const float* __restrict__ Wf, const float* __restrict__ Wi,
                 const float* __restrict__ Wo, const float* __restrict__ Wc,
                 const float* __restrict__ bfv, const float* __restrict__ biv,
                 const float* __restrict__ bov, const float* __restrict__ bcv,
                 const float* __restrict__ X, __half* __restrict__ hT,
                 const float* __restrict__ c0T, int layer) {
    extern __shared__ __align__(128) char sm[];
    __half* B_s = (__half*)(sm + 65536);             // 8 chunks x 4 KB (W hi)
    float*  D_s = (float*)(sm + DS_OFF);             // [2][32 b][33]
    float*  bias_s = (float*)(sm + DS_OFF + 8448);   // [32]
    const uint32_t Au = smem_u32(sm);
    const uint32_t Bu = smem_u32(B_s);

    const int tid = threadIdx.x;
    const int bid = blockIdx.x;
    const int lane = tid & 31;
    const int wid = tid >> 5;
    const int wg = wid >> 2;              // 0: hi(h), 1: lo(h)
    const int wq = wid & 3;
    const int warp_m = (wq >> 1) * 16;    // batch rows 0-15 / 16-31
    const int warp_n = (wq & 1) * 16;     // gate-unit cols 0-15 / 16-31

    // ---- one-time: load W h-part rows (32) as fp16 hi, swizzled ----
    for (int i = tid; i < 32 * 512; i += SCAN_T) {
        int n = i >> 9;          // 0..31 : g*8+u
        int k = i & 511;
        int g = n >> 3, u = n & 7;
        const float* W = (g == 0) ? Wf : (g == 1) ? Wi : (g == 2) ? Wo : Wc;
        float w = W[(size_t)(bid * 8 + u) * 1024 + 512 + k];
        int p  = k >> 6;         // chunk 0..7
        int kk = k & 63;
        int g8 = kk >> 3;
        int off = n * 128 + ((g8 ^ (n & 7)) << 4) + (kk & 7) * 2;
        *(__half*)((char*)B_s + p * 4096 + off) = __float2half_rn(w);
    }
    if (tid < 32) {
        int g = tid >> 3, u = tid & 7;
        const float* Bv = (g == 0) ? bfv : (g == 1) ? biv : (g == 2) ? bov : bcv;
        bias_s[tid] = Bv[bid * 8 + u];
    }
    const int su = tid >> 5;   // unit 0..7
    const int sb = tid & 31;   // batch 0..31
    float c_reg = c0T[(bid * 8 + su) * BATCH + sb];
    __syncthreads();

    const unsigned per_ctr = SCAN_G / NCTR;   // 8 arrivals per counter per step

    for (int t = 0; t < STEPS; t++) {
        const int p = t & 1;
        const __half* hc_hi = hT + (p * 2 + 0) * PLH;
        const __half* hc_lo = hT + (p * 2 + 1) * PLH;
        __half* hn_hi = hT + ((p ^ 1) * 2 + 0) * PLH;
        __half* hn_lo = hT + ((p ^ 1) * 2 + 1) * PLH;

        // ---- stage h: 16 chunks (hi 0-7, lo 8-15); 1 cp.async/thread/chunk ----
        {
            int bb = tid >> 3;
            int g8 = tid & 7;
            uint32_t dsw = (uint32_t)(bb * 128) + (uint32_t)((g8 ^ (bb & 7)) << 4);
            int srcoff = bb * 512 + g8 * 8;
            #pragma unroll
            for (int c = 0; c < 16; c++) {
                const __half* src = ((c < 8) ? hc_hi : hc_lo) + (c & 7) * 64;
                cp_async16(Au + c * 4096 + dsw, src + srcoff);
            }
        }
        CP_COMMIT();
        CP_WAIT(0);
        __syncthreads();

        // ---- mma: 8 chunks per warp-group (wg0: hi(h), wg1: lo(h)) ----
        float acc[2][4];
        #pragma unroll
        for (int ni = 0; ni < 2; ni++)
            #pragma unroll
            for (int q = 0; q < 4; q++) acc[ni][q] = 0.f;

        const uint32_t Abase = Au + (uint32_t)(wg * 32768);
        #pragma unroll 1
        for (int c = 0; c < 8; c++) {
            uint32_t Ab = Abase + c * 4096;
            uint32_t Bb = Bu + c * 4096;
            #pragma unroll
            for (int ks = 0; ks < 4; ks++) {
                uint32_t a[4];
                {
                    int row = warp_m + (lane & 15);
                    int kc  = ks * 2 + (lane >> 4);
                    ldsm4(a, Ab + row * 128 + (uint32_t)((kc ^ (row & 7)) << 4));
                }
                uint32_t bb[4];
                {
                    int row = warp_n + (lane & 7) + ((lane >> 4) << 3);
                    int kc  = ks * 2 + ((lane >> 3) & 1);
                    ldsm4(bb, Bb + row * 128 + (uint32_t)((kc ^ (row & 7)) << 4));
                }
                mma16816(acc[0], a, bb[0], bb[1]);
                mma16816(acc[1], a, bb[2], bb[3]);
            }
        }

        // ---- partial sums to D_s[wg] (stride 33, conflict-free readback) ----
        {
            int r0 = warp_m + (lane >> 2);
            int cc = warp_n + (lane & 3) * 2;
            float* D = D_s + wg * (32 * 33);
            D[r0 * 33 + cc]           = acc[0][0];
            D[r0 * 33 + cc + 1]       = acc[0][1];
            D[(r0 + 8) * 33 + cc]     = acc[0][2];
            D[(r0 + 8) * 33 + cc + 1] = acc[0][3];
            D[r0 * 33 + cc + 8]           = acc[1][0];
            D[r0 * 33 + cc + 9]           = acc[1][1];
            D[(r0 + 8) * 33 + cc + 8]     = acc[1][2];
            D[(r0 + 8) * 33 + cc + 9]     = acc[1][3];
        }
        __syncthreads();

        // ---- state update: one (unit, batch) state per thread ----
        {
            int jg = bid * 8 + su;
            const float* xrow = X + (size_t)(t * BATCH + sb) * GUNITS + jg;
            const float* D0 = D_s + sb * 33;
            const float* D1 = D_s + 32 * 33 + sb * 33;
            float fv = sigmoidf_(D0[su]      + D1[su]      + bias_s[su]      + xrow[0]);
            float iv = sigmoidf_(D0[8 + su]  + D1[8 + su]  + bias_s[8 + su]  + xrow[512]);
            float ov = sigmoidf_(D0[16 + su] + D1[16 + su] + bias_s[16 + su] + xrow[1024]);
            float cv = tanhf    (D0[24 + su] + D1[24 + su] + bias_s[24 + su] + xrow[1536]);
            c_reg = fv * c_reg + iv * cv;
            float h = ov * tanhf(c_reg);
            __half hhi = __float2half_rn(h);
            __half hlo = __float2half_rn(h - __half2float(hhi));
            hn_hi[sb * 512 + jg] = hhi;
            hn_lo[sb * 512 + jg] = hlo;
            size_t ab = (size_t)(t * BATCH + sb) * KPA + jg;
            g_A[ab]       = hhi;
            g_A[ab + 512] = hlo;
        }
        __syncthreads();

        // ---- grid barrier (split counters, 64 arrivals) ----
        if (tid == 0) {
            __threadfence();
            atomicAdd(&g_ctr[layer][(bid & (NCTR - 1)) * CTRPAD], 1u);
        }
        if (tid < NCTR) {
            unsigned target = (unsigned)(t + 1) * per_ctr;
            volatile unsigned* pc = &g_ctr[layer][tid * CTRPAD];
            while (*pc < target) { __nanosleep(32); }
            __threadfence();
        }
        __syncthreads();
    }

    // reset counters for next launch/replay (last block to finish does it)
    if (tid == 0) {
        unsigned v = atomicAdd(&g_fin[layer], 1u);
        if (v == SCAN_G - 1) {
            #pragma unroll
            for (int i = 0; i < NCTR; i++)
                g_ctr[layer][i * CTRPAD] = 0;
            g_fin[layer] = 0;
            __threadfence();
        }
    }
}

// ---------------- launch ----------------
extern "C" void kernel_launch(void* const* d_in, const int* in_sizes, int n_in,
                              void* d_out, int out_size) {
    const float* features = (const float*)d_in[0];
    const int*   captions = (const int*)  d_in[1];
    const float* embw     = (const float*)d_in[2];
    const float* Wf       = (const float*)d_in[3];
    const float* bf       = (const float*)d_in[4];
    const float* Wi       = (const float*)d_in[5];
    const float* bi       = (const float*)d_in[6];
    const float* Wc       = (const float*)d_in[7];
    const float* bc       = (const float*)d_in[8];
    const float* Wo       = (const float*)d_in[9];
    const float* bo       = (const float*)d_in[10];
    const float* out_w    = (const float*)d_in[11];
    const float* out_b    = (const float*)d_in[12];
    const float* ihw      = (const float*)d_in[13];
    const float* ihb      = (const float*)d_in[14];
    const float* icw      = (const float*)d_in[15];
    const float* icb      = (const float*)d_in[16];
    float* out = (float*)d_out;

    cudaFuncSetAttribute(gemm_split_kernel,
                         cudaFuncAttributeMaxDynamicSharedMemorySize, SMEM_DYN);
    cudaFuncSetAttribute(scan_kernel,
                         cudaFuncAttributeMaxDynamicSharedMemorySize, SCAN_SMEM);

    __half* g_B_ptr;  cudaGetSymbolAddress((void**)&g_B_ptr,  g_B);
    __half* g_BW_ptr; cudaGetSymbolAddress((void**)&g_BW_ptr, g_BW);
    float*  g_X_ptr;  cudaGetSymbolAddress((void**)&g_X_ptr,  g_X);
    __half* g_hT0_p;  cudaGetSymbolAddress((void**)&g_hT0_p,  g_hT0p);
    __half* g_hT1_p;  cudaGetSymbolAddress((void**)&g_hT1_p,  g_hT1p);
    float*  g_c0T_p;  cudaGetSymbolAddress((void**)&g_c0T_p,  g_c0T);

    // 1. init state
    init_kernel<<<BATCH, 256>>>(features, ihw, ihb, icw, icb);

    // 2. conversions (weights; independent of recurrence)
    convB_kernel<<<(VOCAB * 512 / 4 + 255) / 256, 256>>>(out_w);
    convWx_kernel<<<(NLAYERS * GUNITS * 512 + 255) / 256, 256>>>(Wf, Wi, Wo, Wc);
    embA_kernel<<<(MROWS * 512 + 255) / 256, 256>>>(captions, embw);

    // 3. X0 = emb @ Wx0^T  (2-term: A=[hi|lo], B chunk wraps modulo 8)
    {
        dim3 grid(GUNITS / 128, MPAD / 128);  // 16 x 16
        gemm_split_kernel<<<grid, 256, SMEM_DYN>>>(g_BW_ptr, nullptr, g_X_ptr,
                                                   GUNITS, 0, 16, 8);
    }

    // 4. layer-0 scan (persistent tensor-core; writes g_A hi/lo rows for X1)
    scan_kernel<<<SCAN_G, SCAN_T, SCAN_SMEM>>>(Wf, Wi, Wo, Wc, bf, bi, bo, bc,
                                               g_X_ptr, g_hT0_p, g_c0T_p, 0);

    // 5. X1 = h0 @ Wx1^T
    {
        dim3 grid(GUNITS / 128, MPAD / 128);
        gemm_split_kernel<<<grid, 256, SMEM_DYN>>>(g_BW_ptr + (size_t)GUNITS * KB,
                                                   nullptr, g_X_ptr, GUNITS, 0, 16, 8);
    }

    // 6. layer-1 scan (writes g_A hi/lo rows for logits)
    scan_kernel<<<SCAN_G, SCAN_T, SCAN_SMEM>>>(Wf + 512 * 1024, Wi + 512 * 1024,
                                               Wo + 512 * 1024, Wc + 512 * 1024,
                                               bf + 512, bi + 512, bo + 512, bc + 512,
                                               g_X_ptr, g_hT1_p, g_c0T_p, 1);

    // 7. logits = h1 @ out_w^T + out_b  (single-term fp16, permuted store)
    {
        dim3 grid(VOCAB / 128, MPAD / 128);   // 250 x 16
        gemm_split_kernel<<<grid, 256, SMEM_DYN>>>(g_B_ptr, out_b, out,
                                                   VOCAB, 1, 8, 8);
    }
}

// round 17
// speedup vs baseline: 1.3183x; 1.0988x over previous
#include <cuda_runtime.h>
#include <cuda_bf16.h>
#include <cuda_fp16.h>
#include <math.h>
#include <stdint.h>

// Problem constants
#define EMBED   512
#define HIDDEN  512
#define VOCAB   32000
#define NLAYERS 2
#define BATCH   32
#define SEQ     64
#define STEPS   (SEQ - 1)          // 63
#define MROWS   (STEPS * BATCH)    // 2016
#define MPAD    2048
#define KPA     1024               // A storage: [Ahi | Alo]
#define KB      512                // B storage: single fp16 copy
#define GUNITS  2048               // 4 gates x 512
#define SCAN_G  64                 // scan grid; 64 <= 148 SMs -> all resident
#define NCTR    8                  // split-barrier counters
#define CTRPAD  32                 // 128B line per counter
#define PLH     (HIDDEN * BATCH)   // 16384 halves per h plane

// ---------------- scratch (no allocations allowed) ----------------
__device__ __half g_A[(size_t)MPAD * KPA];             // 4.2 MB  [hi|lo]
__device__ __half g_B[(size_t)VOCAB * KB];             // 33 MB   out_w hi
__device__ __half g_BW[(size_t)NLAYERS * GUNITS * KB]; // 4.2 MB  Wx hi
__device__ float  g_X[(size_t)MPAD * GUNITS];          // 16.8 MB x-part preacts
// h state: [pingpong][hi/lo][b*512 + k] fp16 planes, per layer
__device__ __half g_hT0p[2][2][PLH];
__device__ __half g_hT1p[2][2][PLH];
__device__ float  g_c0T[HIDDEN * BATCH];
__device__ unsigned g_ctr[2][NCTR * CTRPAD];           // split grid-barrier counters
__device__ unsigned g_fin[2];

__device__ __forceinline__ float sigmoidf_(float x) {
    return 1.0f / (1.0f + expf(-x));
}

// ================= PTX helpers (baseline ISA only) =================
static __device__ __forceinline__ uint32_t smem_u32(const void* p) {
    uint32_t a;
    asm("{ .reg .u64 t; cvta.to.shared.u64 t, %1; cvt.u32.u64 %0, t; }" : "=r"(a) : "l"(p));
    return a;
}
static __device__ __forceinline__ void cp_async16(uint32_t dst, const void* src) {
    asm volatile("cp.async.cg.shared.global [%0], [%1], 16;" :: "r"(dst), "l"(src));
}
#define CP_COMMIT()  asm volatile("cp.async.commit_group;" ::: "memory")
#define CP_WAIT(n)   asm volatile("cp.async.wait_group %0;" :: "n"(n) : "memory")

static __device__ __forceinline__ void ldsm4(uint32_t* r, uint32_t addr) {
    asm volatile("ldmatrix.sync.aligned.m8n8.x4.shared.b16 {%0,%1,%2,%3}, [%4];"
                 : "=r"(r[0]), "=r"(r[1]), "=r"(r[2]), "=r"(r[3]) : "r"(addr));
}
static __device__ __forceinline__ void mma16816(float* c, const uint32_t* a,
                                                uint32_t b0, uint32_t b1) {
    asm volatile("mma.sync.aligned.m16n8k16.row.col.f32.f16.f16.f32 "
                 "{%0,%1,%2,%3}, {%4,%5,%6,%7}, {%8,%9}, {%0,%1,%2,%3};"
                 : "+f"(c[0]), "+f"(c[1]), "+f"(c[2]), "+f"(c[3])
                 : "r"(a[0]), "r"(a[1]), "r"(a[2]), "r"(a[3]), "r"(b0), "r"(b1));
}

// ---------------- init: h0/c0 -> fp16 hi/lo state planes ----------------
__global__ void init_kernel(const float* __restrict__ features,
                            const float* __restrict__ ihw, const float* __restrict__ ihb,
                            const float* __restrict__ icw, const float* __restrict__ icb) {
    __shared__ float feat[EMBED];
    int b = blockIdx.x;
    for (int i = threadIdx.x; i < EMBED; i += blockDim.x)
        feat[i] = features[b * EMBED + i];
    __syncthreads();

    for (int j = threadIdx.x; j < HIDDEN; j += blockDim.x) {
        float ah = ihb[j];
        float ac = icb[j];
        const float4* wh = (const float4*)(ihw + (size_t)j * EMBED);
        const float4* wc = (const float4*)(icw + (size_t)j * EMBED);
        #pragma unroll 4
        for (int e4 = 0; e4 < EMBED / 4; e4++) {
            float4 h4 = wh[e4];
            float4 c4 = wc[e4];
            const float* f = &feat[e4 * 4];
            ah += f[0]*h4.x + f[1]*h4.y + f[2]*h4.z + f[3]*h4.w;
            ac += f[0]*c4.x + f[1]*c4.y + f[2]*c4.z + f[3]*c4.w;
        }
        __half hhi = __float2half_rn(ah);
        __half hlo = __float2half_rn(ah - __half2float(hhi));
        g_hT0p[0][0][b * 512 + j] = hhi;
        g_hT0p[0][1][b * 512 + j] = hlo;
        g_hT1p[0][0][b * 512 + j] = hhi;
        g_hT1p[0][1][b * 512 + j] = hlo;
        g_c0T[j * BATCH + b]      = ac;
    }
}

// ---------------- conversions ----------------
// out_w -> g_B (hi only, K=512); float4-vectorized streaming
__global__ __launch_bounds__(256)
void convB_kernel(const float* __restrict__ w) {
    size_t idx4 = (size_t)blockIdx.x * blockDim.x + threadIdx.x;
    if (idx4 >= (size_t)VOCAB * 512 / 4) return;
    float4 v = ((const float4*)w)[idx4];
    __half2 h01 = __floats2half2_rn(v.x, v.y);
    __half2 h23 = __floats2half2_rn(v.z, v.w);
    __half2* dst = (__half2*)g_B + idx4 * 2;
    dst[0] = h01;
    dst[1] = h23;
}

// Wx (x-part of gate weights, both layers) -> g_BW (hi only, row stride 512)
__global__ __launch_bounds__(256)
void convWx_kernel(const float* __restrict__ Wf, const float* __restrict__ Wi,
                   const float* __restrict__ Wo, const float* __restrict__ Wc) {
    size_t idx = (size_t)blockIdx.x * blockDim.x + threadIdx.x;
    if (idx >= (size_t)NLAYERS * GUNITS * 512) return;
    int k = (int)(idx & 511);
    int r = (int)((idx >> 9) & (GUNITS - 1));
    int l = (int)(idx >> 20);              // 2048*512 = 2^20
    int g = r >> 9;
    int j = r & 511;
    const float* W = (g == 0) ? Wf : (g == 1) ? Wi : (g == 2) ? Wo : Wc;
    g_BW[((size_t)l * GUNITS + r) * KB + k] =
        __float2half_rn(W[(size_t)l * HIDDEN * 1024 + (size_t)j * 1024 + k]);
}

// embeddings gather -> g_A (A-style: [hi | lo]); row m = t*32+b
__global__ __launch_bounds__(256)
void embA_kernel(const int* __restrict__ captions, const float* __restrict__ embw) {
    size_t idx = (size_t)blockIdx.x * blockDim.x + threadIdx.x;
    if (idx >= (size_t)MROWS * 512) return;
    int m = (int)(idx >> 9);
    int k = (int)(idx & 511);
    int t = m >> 5, b = m & 31;
    int tok = captions[b * SEQ + t];
    float x = embw[(size_t)tok * EMBED + k];
    __half hi = __float2half_rn(x);
    __half lo = __float2half_rn(x - __half2float(hi));
    size_t base = (size_t)m * KPA;
    g_A[base + k]       = hi;
    g_A[base + 512 + k] = lo;
}

// ---------------- generic split HMMA GEMM (unchanged, proven) ----------------
#define GBK       64
#define GTILE_B   16384              // 128 rows * 128 B
#define GBUF_B    (2 * GTILE_B)
#define SMEM_DYN  (2 * GBUF_B + 512)

__global__ __launch_bounds__(256)
void gemm_split_kernel(const __half* __restrict__ Bsrc, const float* __restrict__ bias,
                       float* __restrict__ C, int N, int permute, int nch, int nchB) {
    extern __shared__ __align__(128) char sm[];
    const uint32_t smu = smem_u32(sm);
    float* bias_s = (float*)(sm + 2 * GBUF_B);

    const int tid  = threadIdx.x;
    const int wid  = tid >> 5;
    const int lane = tid & 31;
    const int n0 = blockIdx.x * 128;
    const int m0 = blockIdx.y * 128;

    const int warp_m = (wid >> 1) * 32;
    const int warp_n = (wid & 1) * 64;

    if (tid < 128) bias_s[tid] = bias ? bias[n0 + tid] : 0.0f;

    auto load_chunk = [&](int c) {
        const int buf = c & 1;
        const int cb = c & (nchB - 1);
        const uint32_t sA = smu + buf * GBUF_B;
        const uint32_t sB = sA + GTILE_B;
        const __half* Ag = g_A + (size_t)m0 * KPA + c * GBK;
        const __half* Bg = Bsrc + (size_t)n0 * KB + cb * GBK;
        #pragma unroll
        for (int i = 0; i < 4; i++) {
            int idx = i * 256 + tid;
            int r  = idx >> 3;
            int ch = idx & 7;
            uint32_t dst = (uint32_t)(r * 128) + (((uint32_t)(ch ^ (r & 7))) << 4);
            cp_async16(sA + dst, Ag + (size_t)r * KPA + ch * 8);
            cp_async16(sB + dst, Bg + (size_t)r * KB + ch * 8);
        }
        CP_COMMIT();
    };

    float acc[2][8][4];
    #pragma unroll
    for (int mi = 0; mi < 2; mi++)
        #pragma unroll
        for (int ni = 0; ni < 8; ni++)
            #pragma unroll
            for (int q = 0; q < 4; q++) acc[mi][ni][q] = 0.f;

    load_chunk(0);
    load_chunk(1);

    for (int c = 0; c < nch; c++) {
        if (c + 1 < nch) { CP_WAIT(1); } else { CP_WAIT(0); }
        __syncthreads();

        const int buf = c & 1;
        const uint32_t sA = smu + buf * GBUF_B;
        const uint32_t sB = sA + GTILE_B;

        #pragma unroll
        for (int ks = 0; ks < GBK / 16; ks++) {
            uint32_t a[2][4];
            #pragma unroll
            for (int mi = 0; mi < 2; mi++) {
                int row = warp_m + mi * 16 + (lane & 15);
                int kc  = ks * 2 + (lane >> 4);
                uint32_t addr = sA + row * 128 + (((uint32_t)(kc ^ (row & 7))) << 4);
                ldsm4(a[mi], addr);
            }
            uint32_t bfr[4][4];
            #pragma unroll
            for (int nj = 0; nj < 4; nj++) {
                int row = warp_n + nj * 16 + (lane & 7) + ((lane >> 4) << 3);
                int kc  = ks * 2 + ((lane >> 3) & 1);
                uint32_t addr = sB + row * 128 + (((uint32_t)(kc ^ (row & 7))) << 4);
                ldsm4(bfr[nj], addr);
            }
            #pragma unroll
            for (int mi = 0; mi < 2; mi++)
                #pragma unroll
                for (int ni = 0; ni < 8; ni++) {
                    const uint32_t* bp = &bfr[ni >> 1][(ni & 1) * 2];
                    mma16816(acc[mi][ni], a[mi], bp[0], bp[1]);
                }
        }
        __syncthreads();
        if (c + 2 < nch) load_chunk(c + 2);
    }

    #pragma unroll
    for (int mi = 0; mi < 2; mi++) {
        int r0 = m0 + warp_m + mi * 16 + (lane >> 2);
        int r1 = r0 + 8;
        float* orow0 = nullptr;
        float* orow1 = nullptr;
        if (permute) {
            if (r0 < MROWS) {
                int bb = r0 & 31, tt = r0 >> 5;
                orow0 = C + (size_t)(bb * STEPS + tt) * N + n0;
            }
            if (r1 < MROWS) {
                int bb = r1 & 31, tt = r1 >> 5;
                orow1 = C + (size_t)(bb * STEPS + tt) * N + n0;
            }
        } else {
            orow0 = C + (size_t)r0 * N + n0;
            orow1 = C + (size_t)r1 * N + n0;
        }
        #pragma unroll
        for (int ni = 0; ni < 8; ni++) {
            int col = warp_n + ni * 8 + (lane & 3) * 2;
            float b0 = bias_s[col];
            float b1 = bias_s[col + 1];
            if (orow0) {
                float2 v; v.x = acc[mi][ni][0] + b0; v.y = acc[mi][ni][1] + b1;
                *(float2*)&orow0[col] = v;
            }
            if (orow1) {
                float2 v; v.x = acc[mi][ni][2] + b0; v.y = acc[mi][ni][3] + b1;
                *(float2*)&orow1[col] = v;
            }
        }
    }
}

// ---------------- persistent tensor-core scan v3 ----------------
// v2 + pipelined staging: each warp-group stages ONLY its own h half (private
// cp.async group) and syncs via its own named barrier, so the two halves'
// loads overlap and each wg starts mma as soon as its half lands. X tile
// prefetched via cp.async during staging, read from smem in the update.
#define SCAN_T    256
#define DS_OFF    (65536 + 32768)
#define XS_OFF    (DS_OFF + 8448 + 128)
#define SCAN_SMEM (XS_OFF + 4608 + 128)   // A 64K + B 32K + D + bias + X tile

__global__ __launch_bounds__(SCAN_T, 1)
void scan_kernel(const float* __restrict__ Wf, const float* __restrict__ Wi,
                 const float* __restrict__ Wo, const float* __restrict__ Wc,
                 const float* __restrict__ bfv, const float* __restrict__ biv,
                 const float* __restrict__ bov, const float* __restrict__ bcv,
                 const float* __restrict__ X, __half* __restrict__ hT,
                 const float* __restrict__ c0T, int layer) {
    extern __shared__ __align__(128) char sm[];
    __half* B_s = (__half*)(sm + 65536);             // 8 chunks x 4 KB (W hi)
    float*  D_s = (float*)(sm + DS_OFF);             // [2][32 b][33]
    float*  bias_s = (float*)(sm + DS_OFF + 8448);   // [32]
    float*  X_s = (float*)(sm + XS_OFF);             // [32 b][36] (g*8+u in 0..31)
    const uint32_t Au = smem_u32(sm);
    const uint32_t Bu = smem_u32(B_s);
    const uint32_t Xu = smem_u32(X_s);

    const int tid = threadIdx.x;
    const int bid = blockIdx.x;
    const int lane = tid & 31;
    const int wid = tid >> 5;
    const int wg = wid >> 2;              // 0: hi(h), 1: lo(h)
    const int wq = wid & 3;
    const int l128 = tid & 127;           // id within warp-group
    const int warp_m = (wq >> 1) * 16;    // batch rows 0-15 / 16-31
    const int warp_n = (wq & 1) * 16;     // gate-unit cols 0-15 / 16-31

    // ---- one-time: load W h-part rows (32) as fp16 hi, swizzled ----
    for (int i = tid; i < 32 * 512; i += SCAN_T) {
        int n = i >> 9;          // 0..31 : g*8+u
        int k = i & 511;
        int g = n >> 3, u = n & 7;
        const float* W = (g == 0) ? Wf : (g == 1) ? Wi : (g == 2) ? Wo : Wc;
        float w = W[(size_t)(bid * 8 + u) * 1024 + 512 + k];
        int p  = k >> 6;         // chunk 0..7
        int kk = k & 63;
        int g8 = kk >> 3;
        int off = n * 128 + ((g8 ^ (n & 7)) << 4) + (kk & 7) * 2;
        *(__half*)((char*)B_s + p * 4096 + off) = __float2half_rn(w);
    }
    if (tid < 32) {
        int g = tid >> 3, u = tid & 7;
        const float* Bv = (g == 0) ? bfv : (g == 1) ? biv : (g == 2) ? bov : bcv;
        bias_s[tid] = Bv[bid * 8 + u];
    }
    const int su = tid >> 5;   // unit 0..7
    const int sb = tid & 31;   // batch 0..31
    float c_reg = c0T[(bid * 8 + su) * BATCH + sb];
    __syncthreads();

    const unsigned per_ctr = SCAN_G / NCTR;   // 8 arrivals per counter per step

    for (int t = 0; t < STEPS; t++) {
        const int p = t & 1;
        const __half* hc_hi = hT + (p * 2 + 0) * PLH;
        const __half* hc_lo = hT + (p * 2 + 1) * PLH;
        __half* hn_hi = hT + ((p ^ 1) * 2 + 0) * PLH;
        __half* hn_lo = hT + ((p ^ 1) * 2 + 1) * PLH;

        // ---- stage own h half (8 chunks, 2 segs/thread/chunk) -> group 0 ----
        {
            const __half* plane = wg ? hc_lo : hc_hi;
            #pragma unroll
            for (int c = 0; c < 8; c++) {
                const __half* src = plane + c * 64;
                #pragma unroll
                for (int r = 0; r < 2; r++) {
                    int s = l128 + 128 * r;
                    int bb = s >> 3, g8 = s & 7;
                    uint32_t dst = Au + (uint32_t)((wg * 8 + c) * 4096)
                                 + (uint32_t)(bb * 128) + (uint32_t)((g8 ^ (bb & 7)) << 4);
                    cp_async16(dst, src + bb * 512 + g8 * 8);
                }
            }
            CP_COMMIT();   // group 0: own A half
        }
        // ---- X tile prefetch (1 x 16B per thread) -> group 1 ----
        {
            int bb = tid >> 3;
            int g  = (tid >> 1) & 3;
            int hf = tid & 1;
            const float* srcx = X + (size_t)(t * BATCH + bb) * GUNITS
                              + g * 512 + bid * 8 + hf * 4;
            uint32_t dstx = Xu + (uint32_t)((bb * 36 + g * 8 + hf * 4) * 4);
            cp_async16(dstx, srcx);
            CP_COMMIT();   // group 1: X
        }
        CP_WAIT(1);        // own A half landed
        if (wg == 0) asm volatile("bar.sync 1, 128;" ::: "memory");
        else         asm volatile("bar.sync 2, 128;" ::: "memory");

        // ---- mma: 8 chunks on own half ----
        float acc[2][4];
        #pragma unroll
        for (int ni = 0; ni < 2; ni++)
            #pragma unroll
            for (int q = 0; q < 4; q++) acc[ni][q] = 0.f;

        const uint32_t Abase = Au + (uint32_t)(wg * 32768);
        #pragma unroll 1
        for (int c = 0; c < 8; c++) {
            uint32_t Ab = Abase + c * 4096;
            uint32_t Bb = Bu + c * 4096;
            #pragma unroll
            for (int ks = 0; ks < 4; ks++) {
                uint32_t a[4];
                {
                    int row = warp_m + (lane & 15);
                    int kc  = ks * 2 + (lane >> 4);
                    ldsm4(a, Ab + row * 128 + (uint32_t)((kc ^ (row & 7)) << 4));
                }
                uint32_t bb[4];
                {
                    int row = warp_n + (lane & 7) + ((lane >> 4) << 3);
                    int kc  = ks * 2 + ((lane >> 3) & 1);
                    ldsm4(bb, Bb + row * 128 + (uint32_t)((kc ^ (row & 7)) << 4));
                }
                mma16816(acc[0], a, bb[0], bb[1]);
                mma16816(acc[1], a, bb[2], bb[3]);
            }
        }
        CP_WAIT(0);        // X tile landed (overlapped with mma)

        // ---- partial sums to D_s[wg] (stride 33, conflict-free readback) ----
        {
            int r0 = warp_m + (lane >> 2);
            int cc = warp_n + (lane & 3) * 2;
            float* D = D_s + wg * (32 * 33);
            D[r0 * 33 + cc]           = acc[0][0];
            D[r0 * 33 + cc + 1]       = acc[0][1];
            D[(r0 + 8) * 33 + cc]     = acc[0][2];
            D[(r0 + 8) * 33 + cc + 1] = acc[0][3];
            D[r0 * 33 + cc + 8]           = acc[1][0];
            D[r0 * 33 + cc + 9]           = acc[1][1];
            D[(r0 + 8) * 33 + cc + 8]     = acc[1][2];
            D[(r0 + 8) * 33 + cc + 9]     = acc[1][3];
        }
        __syncthreads();

        // ---- state update: one (unit, batch) state per thread ----
        {
            int jg = bid * 8 + su;
            const float* D0 = D_s + sb * 33;
            const float* D1 = D_s + 32 * 33 + sb * 33;
            const float* xs = X_s + sb * 36;
            float fv = sigmoidf_(D0[su]      + D1[su]      + bias_s[su]      + xs[su]);
            float iv = sigmoidf_(D0[8 + su]  + D1[8 + su]  + bias_s[8 + su]  + xs[8 + su]);
            float ov = sigmoidf_(D0[16 + su] + D1[16 + su] + bias_s[16 + su] + xs[16 + su]);
            float cv = tanhf    (D0[24 + su] + D1[24 + su] + bias_s[24 + su] + xs[24 + su]);
            c_reg = fv * c_reg + iv * cv;
            float h = ov * tanhf(c_reg);
            __half hhi = __float2half_rn(h);
            __half hlo = __float2half_rn(h - __half2float(hhi));
            hn_hi[sb * 512 + jg] = hhi;
            hn_lo[sb * 512 + jg] = hlo;
            size_t ab = (size_t)(t * BATCH + sb) * KPA + jg;
            g_A[ab]       = hhi;
            g_A[ab + 512] = hlo;
        }
        __syncthreads();

        // ---- grid barrier (split counters, 64 arrivals) ----
        if (tid == 0) {
            __threadfence();
            atomicAdd(&g_ctr[layer][(bid & (NCTR - 1)) * CTRPAD], 1u);
        }
        if (tid < NCTR) {
            unsigned target = (unsigned)(t + 1) * per_ctr;
            volatile unsigned* pc = &g_ctr[layer][tid * CTRPAD];
            while (*pc < target) { __nanosleep(32); }
            __threadfence();
        }
        __syncthreads();
    }

    // reset counters for next launch/replay (last block to finish does it)
    if (tid == 0) {
        unsigned v = atomicAdd(&g_fin[layer], 1u);
        if (v == SCAN_G - 1) {
            #pragma unroll
            for (int i = 0; i < NCTR; i++)
                g_ctr[layer][i * CTRPAD] = 0;
            g_fin[layer] = 0;
            __threadfence();
        }
    }
}

// ---------------- launch ----------------
extern "C" void kernel_launch(void* const* d_in, const int* in_sizes, int n_in,
                              void* d_out, int out_size) {
    const float* features = (const float*)d_in[0];
    const int*   captions = (const int*)  d_in[1];
    const float* embw     = (const float*)d_in[2];
    const float* Wf       = (const float*)d_in[3];
    const float* bf       = (const float*)d_in[4];
    const float* Wi       = (const float*)d_in[5];
    const float* bi       = (const float*)d_in[6];
    const float* Wc       = (const float*)d_in[7];
    const float* bc       = (const float*)d_in[8];
    const float* Wo       = (const float*)d_in[9];
    const float* bo       = (const float*)d_in[10];
    const float* out_w    = (const float*)d_in[11];
    const float* out_b    = (const float*)d_in[12];
    const float* ihw      = (const float*)d_in[13];
    const float* ihb      = (const float*)d_in[14];
    const float* icw      = (const float*)d_in[15];
    const float* icb      = (const float*)d_in[16];
    float* out = (float*)d_out;

    cudaFuncSetAttribute(gemm_split_kernel,
                         cudaFuncAttributeMaxDynamicSharedMemorySize, SMEM_DYN);
    cudaFuncSetAttribute(scan_kernel,
                         cudaFuncAttributeMaxDynamicSharedMemorySize, SCAN_SMEM);

    __half* g_B_ptr;  cudaGetSymbolAddress((void**)&g_B_ptr,  g_B);
    __half* g_BW_ptr; cudaGetSymbolAddress((void**)&g_BW_ptr, g_BW);
    float*  g_X_ptr;  cudaGetSymbolAddress((void**)&g_X_ptr,  g_X);
    __half* g_hT0_p;  cudaGetSymbolAddress((void**)&g_hT0_p,  g_hT0p);
    __half* g_hT1_p;  cudaGetSymbolAddress((void**)&g_hT1_p,  g_hT1p);
    float*  g_c0T_p;  cudaGetSymbolAddress((void**)&g_c0T_p,  g_c0T);

    // 1. init state
    init_kernel<<<BATCH, 256>>>(features, ihw, ihb, icw, icb);

    // 2. conversions (weights; independent of recurrence)
    convB_kernel<<<(VOCAB * 512 / 4 + 255) / 256, 256>>>(out_w);
    convWx_kernel<<<(NLAYERS * GUNITS * 512 + 255) / 256, 256>>>(Wf, Wi, Wo, Wc);
    embA_kernel<<<(MROWS * 512 + 255) / 256, 256>>>(captions, embw);

    // 3. X0 = emb @ Wx0^T  (2-term: A=[hi|lo], B chunk wraps modulo 8)
    {
        dim3 grid(GUNITS / 128, MPAD / 128);  // 16 x 16
        gemm_split_kernel<<<grid, 256, SMEM_DYN>>>(g_BW_ptr, nullptr, g_X_ptr,
                                                   GUNITS, 0, 16, 8);
    }

    // 4. layer-0 scan (persistent tensor-core; writes g_A hi/lo rows for X1)
    scan_kernel<<<SCAN_G, SCAN_T, SCAN_SMEM>>>(Wf, Wi, Wo, Wc, bf, bi, bo, bc,
                                               g_X_ptr, g_hT0_p, g_c0T_p, 0);

    // 5. X1 = h0 @ Wx1^T
    {
        dim3 grid(GUNITS / 128, MPAD / 128);
        gemm_split_kernel<<<grid, 256, SMEM_DYN>>>(g_BW_ptr + (size_t)GUNITS * KB,
                                                   nullptr, g_X_ptr, GUNITS, 0, 16, 8);
    }

    // 6. layer-1 scan (writes g_A hi/lo rows for logits)
    scan_kernel<<<SCAN_G, SCAN_T, SCAN_SMEM>>>(Wf + 512 * 1024, Wi + 512 * 1024,
                                               Wo + 512 * 1024, Wc + 512 * 1024,
                                               bf + 512, bi + 512, bo + 512, bc + 512,
                                               g_X_ptr, g_hT1_p, g_c0T_p, 1);

    // 7. logits = h1 @ out_w^T + out_b  (single-term fp16, permuted store)
    {
        dim3 grid(VOCAB / 128, MPAD / 128);   // 250 x 16
        gemm_split_kernel<<<grid, 256, SMEM_DYN>>>(g_B_ptr, out_b, out,
                                                   VOCAB, 1, 8, 8);
    }
}